// round 12
// baseline (speedup 1.0000x reference)
#include <cuda_runtime.h>
#include <cuda_fp16.h>
#include <cstdint>
#include <math.h>

// ---------------- problem constants ----------------
#define N_IMG 16
#define CI    64
#define HW    224
#define PLANE (HW*HW)       // 50176
#define CO    128
#define OH    222
#define OW    222
#define KPOS  9
#define KTOT  (CI*KPOS)     // 576

// ---------------- config ----------------
#define THREADS 384
#define NWARPS  12
#define NSM 148
#define ROWS_PER_PHASE 24               // 3552 rows = 148*24, two phases (tile types)

// W smem: [co 128][k 576 pad 584] fp16, row stride 1168B (conflict-free)
#define WK_PAD   584
#define W_ROWB   (WK_PAD*2)              // 1168
#define OFF_W    0
#define W_BYTES  (CO*W_ROWB)             // 149504

// S smem: ring of 4 planes, plane = [col 132][ci 64 pad 72] fp16
#define S_CIPAD  72
#define S_COLB   (S_CIPAD*2)             // 144
#define S_PLANEB (132*S_COLB)            // 19008
#define OFF_S    W_BYTES                 // 149504
#define S_BYTES  (4*S_PLANEB)            // 76032

#define OFF_BIAS (OFF_S + S_BYTES)       // 225536
#define OFF_MIN  (OFF_BIAS + 512)        // 226048 (256 floats: [px][nh])
#define SMEM_TOTAL (OFF_MIN + 1024)      // 227072

#define BAR_ALL()  asm volatile("bar.sync 1, %0;" :: "n"(THREADS) : "memory")
#define BAR_CONS() asm volatile("bar.sync 2, 256;" ::: "memory")

// ---------------- PTX helpers ----------------
__device__ __forceinline__ uint32_t smem_u32(const void* p) {
    uint32_t a;
    asm("{ .reg .u64 t; cvta.to.shared.u64 t, %1; cvt.u32.u64 %0, t; }" : "=r"(a) : "l"(p));
    return a;
}

#define LDSM_X4(r, addr) \
    asm volatile("ldmatrix.sync.aligned.m8n8.x4.shared.b16 {%0,%1,%2,%3}, [%4];" \
        : "=r"((r)[0]), "=r"((r)[1]), "=r"((r)[2]), "=r"((r)[3]) : "r"(addr))

__device__ __forceinline__ void mma_f16(uint32_t* d, const uint32_t* a, const uint32_t* b) {
    asm volatile("mma.sync.aligned.m16n8k16.row.col.f16.f16.f16.f16 "
        "{%0,%1}, {%2,%3,%4,%5}, {%6,%7}, {%0,%1};"
        : "+r"(d[0]), "+r"(d[1])
        : "r"(a[0]), "r"(a[1]), "r"(a[2]), "r"(a[3]), "r"(b[0]), "r"(b[1]));
}

__device__ __forceinline__ uint32_t pack_h16(float lo, float hi) {
    __half2 t = __floats2half2_rn(lo, hi);
    return *(uint32_t*)&t;
}

// ---------------- one staging task: oct (8 ci), 32 cols ----------------
__device__ __forceinline__ void stage_task(
    const float* __restrict__ x, int n, int r_in, int ow0,
    int oct, int cg, int lane, uint32_t sb)
{
    int col = cg * 32 + lane;
    bool stv = (col < 132);
    bool ldv = stv && (ow0 + col < HW);
    const float* gp = x + ((size_t)n * CI + oct * 8) * PLANE
                        + (size_t)r_in * HW + (ow0 + col);
    float v[8];
    #pragma unroll
    for (int q = 0; q < 8; ++q) v[q] = ldv ? gp[(size_t)q * PLANE] : 0.0f;
    if (stv) {
        uint32_t pk0 = pack_h16(v[0], v[1]);
        uint32_t pk1 = pack_h16(v[2], v[3]);
        uint32_t pk2 = pack_h16(v[4], v[5]);
        uint32_t pk3 = pack_h16(v[6], v[7]);
        uint32_t sa = sb + OFF_S + (uint32_t)(r_in & 3) * S_PLANEB
                    + (uint32_t)col * S_COLB + (uint32_t)oct * 16;
        asm volatile("st.shared.v4.b32 [%0], {%1,%2,%3,%4};"
                     :: "r"(sa), "r"(pk0), "r"(pk1), "r"(pk2), "r"(pk3));
    }
}

// ---------------- kernel ----------------
__global__ __launch_bounds__(THREADS, 1)
void conv_min_tanh_u16(const float* __restrict__ x,
                       const float* __restrict__ wgt,
                       const float* __restrict__ bias,
                       float* __restrict__ out)
{
    extern __shared__ char smem[];
    const uint32_t sb = smem_u32(smem);
    const int tid  = threadIdx.x;
    const int lane = tid & 31;
    const int wid  = tid >> 5;
    const bool consumer = (wid < 8);
    const int nh   = wid & 1;         // co half (64 co)
    const int mi0  = wid >> 1;        // first 16-px subtile (0..3)
    __half2* bias_sm = (__half2*)(smem + OFF_BIAS);
    float*   min_sm  = (float*)(smem + OFF_MIN);

    // ---- stage weights once: W[co][k], k = kp*64 + ci, fp16 ----
    for (int i = tid; i < CO * KTOT; i += THREADS) {
        int co  = i / KTOT;
        int rem = i - co * KTOT;
        int ci  = rem / KPOS;
        int kp  = rem - ci * KPOS;
        int k   = kp * 64 + ci;
        *(__half*)(smem + OFF_W + co * W_ROWB + k * 2) = __float2half_rn(wgt[i]);
    }
    if (tid < CO / 2) {
        bias_sm[tid] = __floats2half2_rn(bias[2 * tid], bias[2 * tid + 1]);
    }
    __syncthreads();

    // bias regs: co pair = nh*64 + nt*8 + 2*(lane&3)
    __half2 bh[8];
    #pragma unroll
    for (int nt = 0; nt < 8; ++nt) {
        int c = nh * 32 + nt * 4 + (lane & 3);
        bh[nt] = bias_sm[c];
    }

    // A lane-offset within plane (per mi added later); B base
    const uint32_t aOff = (uint32_t)(lane & 15) * S_COLB + (uint32_t)(lane >> 4) * 16;
    const uint32_t bBase = sb + OFF_W
        + (uint32_t)(nh * 64 + (lane & 7) + ((lane >> 4) & 1) * 8) * W_ROWB
        + (uint32_t)((lane >> 3) & 1) * 16;

    int prev_tt = -1;

    for (int iter = 0; iter < 2 * ROWS_PER_PHASE; ++iter) {
        const int tt  = iter / ROWS_PER_PHASE;            // 0: [0,128), 1: [126,222)
        const int i   = iter - tt * ROWS_PER_PHASE;
        const int R   = blockIdx.x * ROWS_PER_PHASE + i;  // global row id
        const int n   = R / OH;
        const int oh  = R - n * OH;
        const int ow0 = tt ? (OW - 96) : 0;               // 126 or 0
        const int npx = tt ? 96 : 128;

        // ---- fresh staging on phase flip / image wrap / start ----
        if (iter == 0 || tt != prev_tt || oh == 0) {
            #pragma unroll 1
            for (int j = 0; j < 10; ++j) {
                int tk = wid + NWARPS * j;
                if (tk >= 120) break;
                int pl  = tk / 40;
                int r   = tk - pl * 40;
                int oct = r / 5;
                int cg  = r - oct * 5;
                stage_task(x, n, oh + pl, ow0, oct, cg, lane, sb);
            }
            BAR_ALL();
            prev_tt = tt;
        }
        // invariant: planes oh, oh+1, oh+2 staged & visible

        const bool next_same = (i + 1 < ROWS_PER_PHASE) && (oh + 1 < OH);

        if (consumer) {
            // nmi: tile1 always 2 slots (mi0, mi0+4); tile2: only warps 0-3
            const bool two = (tt == 0) || (wid < 4);

            uint32_t acc[2][8][2];
            #pragma unroll
            for (int s = 0; s < 2; ++s)
                #pragma unroll
                for (int nt = 0; nt < 8; ++nt) {
                    acc[s][nt][0] = 0u;
                    acc[s][nt][1] = 0u;
                }

            const uint32_t mB0 = (uint32_t)(mi0 * 16) * S_COLB;
            const uint32_t mB1 = mB0 + (uint32_t)(4 * 16) * S_COLB;

            #pragma unroll 1
            for (int kp = 0; kp < KPOS; ++kp) {
                const int kh = kp / 3, kw = kp - 3 * (kp / 3);
                const uint32_t aP = sb + OFF_S + (uint32_t)((oh + kh) & 3) * S_PLANEB
                                  + (uint32_t)kw * S_COLB + aOff;
                const uint32_t kB = (uint32_t)(kp * 64) * 2;
                #pragma unroll
                for (int ks = 0; ks < 4; ++ks) {
                    uint32_t bf[4][4];
                    #pragma unroll
                    for (int ntp = 0; ntp < 4; ++ntp)
                        LDSM_X4(bf[ntp], bBase + (uint32_t)ntp * 16 * W_ROWB + kB + ks * 32);
                    uint32_t a0[4];
                    LDSM_X4(a0, aP + mB0 + ks * 32);
                    #pragma unroll
                    for (int ntp = 0; ntp < 4; ++ntp) {
                        mma_f16(acc[0][2 * ntp + 0], a0, &bf[ntp][0]);
                        mma_f16(acc[0][2 * ntp + 1], a0, &bf[ntp][2]);
                    }
                    if (two) {
                        uint32_t a1[4];
                        LDSM_X4(a1, aP + mB1 + ks * 32);
                        #pragma unroll
                        for (int ntp = 0; ntp < 4; ++ntp) {
                            mma_f16(acc[1][2 * ntp + 0], a1, &bf[ntp][0]);
                            mma_f16(acc[1][2 * ntp + 1], a1, &bf[ntp][2]);
                        }
                    }
                }
            }

            // ---- epilogue: bias + min over 64 co per slot ----
            #pragma unroll
            for (int s = 0; s < 2; ++s) {
                if (s == 1 && !two) break;
                __half2 h0 = __floats2half2_rn(6.5e4f, 6.5e4f);
                __half2 h1 = h0;
                #pragma unroll
                for (int nt = 0; nt < 8; ++nt) {
                    h0 = __hmin2(h0, __hadd2(*(__half2*)&acc[s][nt][0], bh[nt]));
                    h1 = __hmin2(h1, __hadd2(*(__half2*)&acc[s][nt][1], bh[nt]));
                }
                float2 f0 = __half22float2(h0);
                float2 f1 = __half22float2(h1);
                float v0 = fminf(f0.x, f0.y);
                float v1 = fminf(f1.x, f1.y);
                v0 = fminf(v0, __shfl_xor_sync(0xFFFFFFFFu, v0, 1));
                v0 = fminf(v0, __shfl_xor_sync(0xFFFFFFFFu, v0, 2));
                v1 = fminf(v1, __shfl_xor_sync(0xFFFFFFFFu, v1, 1));
                v1 = fminf(v1, __shfl_xor_sync(0xFFFFFFFFu, v1, 2));
                if ((lane & 3) == 0) {
                    int px0 = (mi0 + s * 4) * 16 + (lane >> 2);
                    min_sm[px0 * 2 + nh]       = v0;
                    min_sm[(px0 + 8) * 2 + nh] = v1;
                }
            }
            BAR_CONS();
            if (tid < npx) {
                float2 q = *(const float2*)(min_sm + tid * 2);
                float m = fminf(q.x, q.y);
                out[((size_t)n * OH + oh) * OW + ow0 + tid] = tanhf(tanhf(m));
            }
        } else {
            // ---- producers (4 warps): stage plane oh+3 (10 tasks/warp) ----
            if (next_same) {
                const int pw = wid - 8;
                #pragma unroll
                for (int j = 0; j < 10; ++j) {
                    int tk  = pw + 4 * j;     // 0..39
                    int oct = tk / 5;
                    int cg  = tk - oct * 5;
                    stage_task(x, n, oh + 3, ow0, oct, cg, lane, sb);
                }
            }
        }

        BAR_ALL();  // plane oh+3 visible; min_sm reads done; ring slot retire
    }
}

extern "C" void kernel_launch(void* const* d_in, const int* in_sizes, int n_in,
                              void* d_out, int out_size)
{
    const float* x    = (const float*)d_in[0];
    const float* wgt  = (const float*)d_in[1];
    const float* bias = (const float*)d_in[2];
    float* out        = (float*)d_out;

    cudaFuncSetAttribute(conv_min_tanh_u16,
                         cudaFuncAttributeMaxDynamicSharedMemorySize, SMEM_TOTAL);
    conv_min_tanh_u16<<<NSM, THREADS, SMEM_TOTAL>>>(x, wgt, bias, out);
}

// round 13
// speedup vs baseline: 1.0277x; 1.0277x over previous
#include <cuda_runtime.h>
#include <cuda_fp16.h>
#include <cstdint>
#include <math.h>

// ---------------- problem constants ----------------
#define N_IMG 16
#define CI    64
#define HW    224
#define PLANE (HW*HW)       // 50176
#define CO    128
#define OH    222
#define OW    222
#define KPOS  9
#define KTOT  (CI*KPOS)     // 576

// ---------------- config ----------------
#define THREADS 384
#define NSM 148
#define ROWS_PER_CTA 24     // 148*24 = 3552 = 16*222 rows total

// W smem: 8 blocks (kp 0..7), block = [co 128][ci 64] fp16, swizzled, 16384 B each
#define W_BLOCK  16384
#define OFF_W    0
#define W_BYTES  (8*W_BLOCK)             // 131072

// S smem: ring of 3 full-width planes, plane = [col 224][ci 64] fp16, swizzled
#define S_PLANEB 28672                   // 224*128
#define OFF_S    W_BYTES                 // 131072
#define S_BYTES  (3*S_PLANEB)            // 86016

#define OFF_BIAS (OFF_S + S_BYTES)       // 217088 (64 half2 = 256B, pad 512)
#define OFF_MIN  (OFF_BIAS + 512)        // 217600 (224 px * 2 nh floats = 1792B)
#define SMEM_TOTAL (OFF_MIN + 1792)      // 219392

#define BAR_ALL()  asm volatile("bar.sync 1, %0;" :: "n"(THREADS) : "memory")

// kp8 B-fragments, pre-packed in mma lane order: [nh][lane][ks][ntp][j]
__device__ uint4 g_kp8[1024];

// ---------------- PTX helpers ----------------
__device__ __forceinline__ uint32_t smem_u32(const void* p) {
    uint32_t a;
    asm("{ .reg .u64 t; cvta.to.shared.u64 t, %1; cvt.u32.u64 %0, t; }" : "=r"(a) : "l"(p));
    return a;
}

#define LDSM_X4(r, addr) \
    asm volatile("ldmatrix.sync.aligned.m8n8.x4.shared.b16 {%0,%1,%2,%3}, [%4];" \
        : "=r"((r)[0]), "=r"((r)[1]), "=r"((r)[2]), "=r"((r)[3]) : "r"(addr))

__device__ __forceinline__ void mma_f16(uint32_t* d, const uint32_t* a, const uint32_t* b) {
    asm volatile("mma.sync.aligned.m16n8k16.row.col.f16.f16.f16.f16 "
        "{%0,%1}, {%2,%3,%4,%5}, {%6,%7}, {%0,%1};"
        : "+r"(d[0]), "+r"(d[1])
        : "r"(a[0]), "r"(a[1]), "r"(a[2]), "r"(a[3]), "r"(b[0]), "r"(b[1]));
}

__device__ __forceinline__ uint32_t pack_h16(float lo, float hi) {
    __half2 t = __floats2half2_rn(lo, hi);
    return *(uint32_t*)&t;
}

// ---------------- prep kernel: pack kp=8 weight B-fragments ----------------
// m16n8k16 B frag: thread t, n8 group: b0,b1 = B[n=t/4][k=2(t%4)+{0,1}],
// b2,b3 = same n, k+8. Our bf[4] = {(co,k),(co,k+8),(co+8,k),(co+8,k+8)} pairs.
__global__ void prep_kp8(const float* __restrict__ wgt) {
    int i = blockIdx.x * 256 + threadIdx.x;    // 0..4095
    int j    = i & 3;
    int ntp  = (i >> 2) & 3;
    int ks   = (i >> 4) & 3;
    int lane = (i >> 6) & 31;
    int nh   = (i >> 11) & 1;
    int co = nh * 64 + ntp * 16 + (lane >> 2) + ((j >> 1) & 1) * 8;
    int ci = ks * 16 + 2 * (lane & 3) + (j & 1) * 8;
    float f0 = wgt[co * KTOT + ci * KPOS + 8];
    float f1 = wgt[co * KTOT + (ci + 1) * KPOS + 8];
    ((uint32_t*)g_kp8)[i] = pack_h16(f0, f1);
}

// ---------------- staging: full-width plane task (oct of 8 ci, 32 cols) ----
__device__ __forceinline__ void stage_full(
    const float* __restrict__ x, int n, int r_in,
    int oct, int cg, int lane, uint32_t sb)
{
    int col = cg * 32 + lane;                  // 0..223, always valid
    const float* gp = x + ((size_t)n * CI + oct * 8) * PLANE
                        + (size_t)r_in * HW + col;
    float v[8];
    #pragma unroll
    for (int q = 0; q < 8; ++q) v[q] = gp[(size_t)q * PLANE];
    uint32_t pk0 = pack_h16(v[0], v[1]);
    uint32_t pk1 = pack_h16(v[2], v[3]);
    uint32_t pk2 = pack_h16(v[4], v[5]);
    uint32_t pk3 = pack_h16(v[6], v[7]);
    int slot = r_in % 3;
    uint32_t byte = (uint32_t)col * 128 + (uint32_t)oct * 16;
    uint32_t phys = byte ^ (((uint32_t)col & 7) << 4);
    uint32_t sa = sb + OFF_S + (uint32_t)slot * S_PLANEB + phys;
    asm volatile("st.shared.v4.b32 [%0], {%1,%2,%3,%4};"
                 :: "r"(sa), "r"(pk0), "r"(pk1), "r"(pk2), "r"(pk3));
}

// ---------------- kernel ----------------
__global__ __launch_bounds__(THREADS, 1)
void conv_min_tanh_fw(const float* __restrict__ x,
                      const float* __restrict__ wgt,
                      const float* __restrict__ bias,
                      float* __restrict__ out)
{
    extern __shared__ char smem[];
    const uint32_t sb = smem_u32(smem);
    const int tid  = threadIdx.x;
    const int lane = tid & 31;
    const int wid  = tid >> 5;
    const bool consumer = (wid < 8);
    const int nh   = wid & 1;
    // slot table: pair = wid>>1 -> start {0,4,7,10}, cnt {4,3,3,4}
    const int pair  = wid >> 1;
    const int start = pair * 3 + (pair >= 1 ? 1 : 0);
    const int cnt   = (pair == 0 || pair == 3) ? 4 : 3;
    float* min_sm = (float*)(smem + OFF_MIN);

    // ---- stage weights (kp 0..7) into swizzled blocks ----
    for (int i2 = tid; i2 < CO * KTOT; i2 += THREADS) {
        int co  = i2 / KTOT;
        int rem = i2 - co * KTOT;
        int ci  = rem / KPOS;
        int kp  = rem - ci * KPOS;
        if (kp < 8) {
            uint32_t byte = (uint32_t)(co * 128 + ci * 2);
            uint32_t phys = byte ^ (((uint32_t)co & 7) << 4);
            *(__half*)(smem + OFF_W + kp * W_BLOCK + phys) = __float2half_rn(wgt[i2]);
        }
    }
    if (tid < CO / 2)
        ((__half2*)(smem + OFF_BIAS))[tid] = __floats2half2_rn(bias[2 * tid], bias[2 * tid + 1]);
    __syncthreads();

    // bias regs: co pair = nh*64 + nt*8 + 2*(lane&3)
    __half2 bh[8];
    #pragma unroll
    for (int nt = 0; nt < 8; ++nt)
        bh[nt] = ((__half2*)(smem + OFF_BIAS))[nh * 32 + nt * 4 + (lane & 3)];

    // addressing precomputes
    const uint32_t qA   = lane & 15;            // A row base (add kw)
    const uint32_t hi16 = (uint32_t)(lane >> 4) * 16;
    const uint32_t bco  = (uint32_t)(nh * 64 + (lane & 7) + ((lane >> 4) & 1) * 8);
    const uint32_t bBase2 = sb + OFF_W + bco * 128;
    const uint32_t xorb   = (bco & 7) << 4;
    const uint32_t c16    = (uint32_t)((lane >> 3) & 1) * 16;
    const uint4* kp8p = g_kp8 + (size_t)(nh * 32 + lane) * 16;

    for (int it = 0; it < ROWS_PER_CTA; ++it) {
        const int R  = blockIdx.x * ROWS_PER_CTA + it;
        const int n  = R / OH;
        const int oh = R - n * OH;

        // ---- strip entry: stage planes oh..oh+2 (168 tasks, 12 warps) ----
        if (it == 0 || oh == 0) {
            #pragma unroll 1
            for (int j2 = 0; j2 < 14; ++j2) {
                int tk = wid + 12 * j2;
                if (tk >= 168) break;
                int pl  = tk / 56;
                int r2  = tk - pl * 56;
                int oct = r2 / 7;
                int cg  = r2 - oct * 7;
                stage_full(x, n, oh + pl, oct, cg, lane, sb);
            }
            BAR_ALL();
        }

        const bool next_same = (it + 1 < ROWS_PER_CTA) && (oh + 1 < OH);

        uint32_t pfp[14][4];   // producers' prefetched plane (regs)

        if (consumer) {
            uint32_t acc[4][8][2];
            #pragma unroll
            for (int s = 0; s < 4; ++s)
                #pragma unroll
                for (int nt = 0; nt < 8; ++nt) { acc[s][nt][0] = 0u; acc[s][nt][1] = 0u; }

            // ---- kp 0..7: B from smem blocks ----
            #pragma unroll 1
            for (int kp = 0; kp < 8; ++kp) {
                const int kh = kp / 3, kw = kp - 3 * kh;
                const uint32_t pb  = sb + OFF_S + (uint32_t)((oh + kh) % 3) * S_PLANEB;
                const uint32_t q   = (uint32_t)kw + qA;
                const uint32_t q13 = 206u + (uint32_t)kw + qA;
                #pragma unroll
                for (int ks = 0; ks < 4; ++ks) {
                    const uint32_t koff = (uint32_t)ks * 32 + hi16;
                    const uint32_t aKs  = pb + ((q * 128 + koff) ^ ((q & 7) << 4));
                    const uint32_t a13  = pb + ((q13 * 128 + koff) ^ ((q13 & 7) << 4));
                    uint32_t bf[4][4];
                    const uint32_t bAdr = bBase2 + (uint32_t)kp * W_BLOCK
                                        + (((uint32_t)ks * 32 + c16) ^ xorb);
                    #pragma unroll
                    for (int ntp = 0; ntp < 4; ++ntp)
                        LDSM_X4(bf[ntp], bAdr + (uint32_t)ntp * 2048);
                    #pragma unroll
                    for (int s = 0; s < 4; ++s) {
                        if (s >= cnt) break;
                        const int st = start + s;
                        const uint32_t aAdr = (st < 13) ? (aKs + (uint32_t)st * 2048) : a13;
                        uint32_t a[4];
                        LDSM_X4(a, aAdr);
                        #pragma unroll
                        for (int ntp = 0; ntp < 4; ++ntp) {
                            mma_f16(acc[s][2 * ntp + 0], a, &bf[ntp][0]);
                            mma_f16(acc[s][2 * ntp + 1], a, &bf[ntp][2]);
                        }
                    }
                }
            }

            // ---- kp 8 (kh=2, kw=2): B from pre-packed gmem blob ----
            {
                const uint32_t pb  = sb + OFF_S + (uint32_t)((oh + 2) % 3) * S_PLANEB;
                const uint32_t q   = 2u + qA;
                const uint32_t q13 = 208u + qA;
                #pragma unroll
                for (int ks = 0; ks < 4; ++ks) {
                    const uint32_t koff = (uint32_t)ks * 32 + hi16;
                    const uint32_t aKs  = pb + ((q * 128 + koff) ^ ((q & 7) << 4));
                    const uint32_t a13  = pb + ((q13 * 128 + koff) ^ ((q13 & 7) << 4));
                    uint4 u0 = kp8p[ks * 4 + 0];
                    uint4 u1 = kp8p[ks * 4 + 1];
                    uint4 u2 = kp8p[ks * 4 + 2];
                    uint4 u3 = kp8p[ks * 4 + 3];
                    uint32_t bf[4][4] = {
                        {u0.x, u0.y, u0.z, u0.w},
                        {u1.x, u1.y, u1.z, u1.w},
                        {u2.x, u2.y, u2.z, u2.w},
                        {u3.x, u3.y, u3.z, u3.w}
                    };
                    #pragma unroll
                    for (int s = 0; s < 4; ++s) {
                        if (s >= cnt) break;
                        const int st = start + s;
                        const uint32_t aAdr = (st < 13) ? (aKs + (uint32_t)st * 2048) : a13;
                        uint32_t a[4];
                        LDSM_X4(a, aAdr);
                        #pragma unroll
                        for (int ntp = 0; ntp < 4; ++ntp) {
                            mma_f16(acc[s][2 * ntp + 0], a, &bf[ntp][0]);
                            mma_f16(acc[s][2 * ntp + 1], a, &bf[ntp][2]);
                        }
                    }
                }
            }

            // ---- epilogue: bias + min over 64 co per slot ----
            #pragma unroll
            for (int s = 0; s < 4; ++s) {
                if (s >= cnt) break;
                const int st  = start + s;
                const int pxb = (st < 13) ? st * 16 : 206;
                __half2 h0 = __floats2half2_rn(6.5e4f, 6.5e4f);
                __half2 h1 = h0;
                #pragma unroll
                for (int nt = 0; nt < 8; ++nt) {
                    h0 = __hmin2(h0, __hadd2(*(__half2*)&acc[s][nt][0], bh[nt]));
                    h1 = __hmin2(h1, __hadd2(*(__half2*)&acc[s][nt][1], bh[nt]));
                }
                float2 f0 = __half22float2(h0);
                float2 f1 = __half22float2(h1);
                float v0 = fminf(f0.x, f0.y);
                float v1 = fminf(f1.x, f1.y);
                v0 = fminf(v0, __shfl_xor_sync(0xFFFFFFFFu, v0, 1));
                v0 = fminf(v0, __shfl_xor_sync(0xFFFFFFFFu, v0, 2));
                v1 = fminf(v1, __shfl_xor_sync(0xFFFFFFFFu, v1, 1));
                v1 = fminf(v1, __shfl_xor_sync(0xFFFFFFFFu, v1, 2));
                if ((lane & 3) == 0) {
                    int row = lane >> 2;
                    min_sm[(pxb + row) * 2 + nh]     = v0;
                    min_sm[(pxb + 8 + row) * 2 + nh] = v1;
                }
            }
        } else {
            // ---- producers: prefetch plane oh+3 into regs (14 tasks/warp) ----
            if (next_same) {
                const int pw = wid - 8;
                #pragma unroll 2
                for (int j2 = 0; j2 < 14; ++j2) {
                    int tk  = pw + 4 * j2;        // 0..55
                    int oct = tk / 7;
                    int cg  = tk - oct * 7;
                    int col = cg * 32 + lane;
                    const float* gp = x + ((size_t)n * CI + oct * 8) * PLANE
                                        + (size_t)(oh + 3) * HW + col;
                    float v[8];
                    #pragma unroll
                    for (int q = 0; q < 8; ++q) v[q] = gp[(size_t)q * PLANE];
                    pfp[j2][0] = pack_h16(v[0], v[1]);
                    pfp[j2][1] = pack_h16(v[2], v[3]);
                    pfp[j2][2] = pack_h16(v[4], v[5]);
                    pfp[j2][3] = pack_h16(v[6], v[7]);
                }
            }
        }

        BAR_ALL();  // min_sm written; consumers done reading ring planes

        // output (first 222 threads — all consumers)
        if (tid < OW) {
            float2 qq = *(const float2*)(min_sm + tid * 2);
            float m = fminf(qq.x, qq.y);
            out[((size_t)n * OH + oh) * OW + tid] = tanhf(tanhf(m));
        }

        // producers: publish plane oh+3 into retired slot (oh%3)
        if (!consumer && next_same) {
            const int pw = wid - 8;
            const uint32_t slotB = sb + OFF_S + (uint32_t)((oh + 3) % 3) * S_PLANEB;
            #pragma unroll 2
            for (int j2 = 0; j2 < 14; ++j2) {
                int tk  = pw + 4 * j2;
                int oct = tk / 7;
                int cg  = tk - oct * 7;
                int col = cg * 32 + lane;
                uint32_t byte = (uint32_t)col * 128 + (uint32_t)oct * 16;
                uint32_t phys = byte ^ (((uint32_t)col & 7) << 4);
                uint32_t sa = slotB + phys;
                asm volatile("st.shared.v4.b32 [%0], {%1,%2,%3,%4};"
                             :: "r"(sa), "r"(pfp[j2][0]), "r"(pfp[j2][1]),
                                "r"(pfp[j2][2]), "r"(pfp[j2][3]));
            }
        }

        BAR_ALL();  // plane visible; min_sm reads done
    }
}

extern "C" void kernel_launch(void* const* d_in, const int* in_sizes, int n_in,
                              void* d_out, int out_size)
{
    const float* x    = (const float*)d_in[0];
    const float* wgt  = (const float*)d_in[1];
    const float* bias = (const float*)d_in[2];
    float* out        = (float*)d_out;

    prep_kp8<<<16, 256>>>(wgt);

    cudaFuncSetAttribute(conv_min_tanh_fw,
                         cudaFuncAttributeMaxDynamicSharedMemorySize, SMEM_TOTAL);
    conv_min_tanh_fw<<<NSM, THREADS, SMEM_TOTAL>>>(x, wgt, bias, out);
}

// round 14
// speedup vs baseline: 1.1875x; 1.1555x over previous
#include <cuda_runtime.h>
#include <cuda_fp16.h>
#include <cstdint>
#include <math.h>

// ---------------- problem constants ----------------
#define N_IMG 16
#define CI    64
#define HW    224
#define PLANE (HW*HW)       // 50176
#define CO    128
#define OH    222
#define OW    222
#define KPOS  9
#define KTOT  (CI*KPOS)     // 576

// ---------------- config ----------------
#define THREADS 384
#define NWARPS  12
#define NSM 152                          // GB300 has 152 SMs
#define TILES_TOTAL (N_IMG*OH*2)         // 7104

// W smem: [co 128][k 576 pad 584] fp16, row stride 1168B (conflict-free)
#define WK_PAD   584
#define W_ROWB   (WK_PAD*2)              // 1168
#define OFF_W    0
#define W_BYTES  (CO*W_ROWB)             // 149504

// S smem: ring of 4 planes, plane = [col 132][ci 64 pad 72] fp16
#define S_CIPAD  72
#define S_COLB   (S_CIPAD*2)             // 144
#define S_PLANEB (132*S_COLB)            // 19008
#define OFF_S    W_BYTES                 // 149504
#define S_BYTES  (4*S_PLANEB)            // 76032

#define OFF_BIAS (OFF_S + S_BYTES)       // 225536
#define OFF_MIN  (OFF_BIAS + 512)        // 226048 (256 floats)
#define SMEM_TOTAL (OFF_MIN + 1024)      // 227072

// named barriers
#define BAR_ALL()        asm volatile("bar.sync 1, %0;" :: "n"(THREADS) : "memory")
#define BAR_PAIR(idx)    asm volatile("bar.sync %0, 64;" :: "r"(3 + (idx)) : "memory")

// ---------------- PTX helpers ----------------
__device__ __forceinline__ uint32_t smem_u32(const void* p) {
    uint32_t a;
    asm("{ .reg .u64 t; cvta.to.shared.u64 t, %1; cvt.u32.u64 %0, t; }" : "=r"(a) : "l"(p));
    return a;
}

#define LDSM_X4(r, addr) \
    asm volatile("ldmatrix.sync.aligned.m8n8.x4.shared.b16 {%0,%1,%2,%3}, [%4];" \
        : "=r"((r)[0]), "=r"((r)[1]), "=r"((r)[2]), "=r"((r)[3]) : "r"(addr))

__device__ __forceinline__ void mma_f16(uint32_t* d, const uint32_t* a, const uint32_t* b) {
    asm volatile("mma.sync.aligned.m16n8k16.row.col.f16.f16.f16.f16 "
        "{%0,%1}, {%2,%3,%4,%5}, {%6,%7}, {%0,%1};"
        : "+r"(d[0]), "+r"(d[1])
        : "r"(a[0]), "r"(a[1]), "r"(a[2]), "r"(a[3]), "r"(b[0]), "r"(b[1]));
}

__device__ __forceinline__ uint32_t pack_h16(float lo, float hi) {
    __half2 t = __floats2half2_rn(lo, hi);
    return *(uint32_t*)&t;
}

// ---------------- one staging task: oct (8 ci), 32 cols ----------------
__device__ __forceinline__ void stage_task(
    const float* __restrict__ x, int n, int r_in, int ow0,
    int oct, int cg, int lane, uint32_t sb)
{
    int col = cg * 32 + lane;
    bool stv = (col < 132);
    bool ldv = stv && (ow0 + col < HW);
    const float* gp = x + ((size_t)n * CI + oct * 8) * PLANE
                        + (size_t)r_in * HW + (ow0 + col);
    float v[8];
    #pragma unroll
    for (int q = 0; q < 8; ++q) v[q] = ldv ? gp[(size_t)q * PLANE] : 0.0f;
    if (stv) {
        uint32_t pk0 = pack_h16(v[0], v[1]);
        uint32_t pk1 = pack_h16(v[2], v[3]);
        uint32_t pk2 = pack_h16(v[4], v[5]);
        uint32_t pk3 = pack_h16(v[6], v[7]);
        uint32_t sa = sb + OFF_S + (uint32_t)(r_in & 3) * S_PLANEB
                    + (uint32_t)col * S_COLB + (uint32_t)oct * 16;
        asm volatile("st.shared.v4.b32 [%0], {%1,%2,%3,%4};"
                     :: "r"(sa), "r"(pk0), "r"(pk1), "r"(pk2), "r"(pk3));
    }
}

// ---------------- kernel ----------------
__global__ __launch_bounds__(THREADS, 1)
void conv_min_tanh_152(const float* __restrict__ x,
                       const float* __restrict__ wgt,
                       const float* __restrict__ bias,
                       float* __restrict__ out)
{
    extern __shared__ char smem[];
    const uint32_t sb = smem_u32(smem);
    const int tid  = threadIdx.x;
    const int lane = tid & 31;
    const int wid  = tid >> 5;
    const bool consumer = (wid < 8);
    const int wm   = wid & 3;        // consumer: pixel group (32 px)
    const int wn   = (wid >> 2) & 1; // consumer: co half (64 co)
    __half2* bias_sm = (__half2*)(smem + OFF_BIAS);
    float*   min_sm  = (float*)(smem + OFF_MIN);

    // ---- stage weights once (vectorized float4 loads) ----
    // 73728 elems = 18432 float4; 4 | KTOT so no co crossing within a float4.
    for (int i4 = tid; i4 < (CO * KTOT) / 4; i4 += THREADS) {
        float4 w4 = ((const float4*)wgt)[i4];
        int base = i4 * 4;
        int co   = base / KTOT;
        int rem  = base - co * KTOT;          // ci*9 + kp for element 0
        float vv[4] = {w4.x, w4.y, w4.z, w4.w};
        #pragma unroll
        for (int j = 0; j < 4; ++j) {
            int r2 = rem + j;
            int ci = r2 / KPOS;
            int kp = r2 - ci * KPOS;
            int k  = kp * 64 + ci;
            *(__half*)(smem + OFF_W + co * W_ROWB + k * 2) = __float2half_rn(vv[j]);
        }
    }
    if (tid < CO / 2) {
        bias_sm[tid] = __floats2half2_rn(bias[2 * tid], bias[2 * tid + 1]);
    }
    __syncthreads();

    // per-thread bias regs: co pair = wn*64 + nt*8 + 2*(lane&3)
    __half2 bh[8];
    #pragma unroll
    for (int nt = 0; nt < 8; ++nt) {
        int c = wn * 32 + nt * 4 + (lane & 3);
        bh[nt] = bias_sm[c];
    }

    // ldmatrix lane address components
    const uint32_t aCol = (uint32_t)(wm * 32 + (lane & 15)) * S_COLB
                        + (uint32_t)(lane >> 4) * 16;
    const uint32_t bBase = sb + OFF_W
        + (uint32_t)(wn * 64 + (lane & 7) + ((lane >> 4) & 1) * 8) * W_ROWB
        + (uint32_t)((lane >> 3) & 1) * 16;

    // prorated contiguous tile range over 152 CTAs
    const int tStart = (int)(((long long)blockIdx.x * TILES_TOTAL) / NSM);
    const int tEnd   = (int)(((long long)(blockIdx.x + 1) * TILES_TOTAL) / NSM);

    int prev_strip = -1;

    for (int t = tStart; t < tEnd; ++t) {
        const int strip = t / OH;              // 0..31 : (n, half)
        const int oh    = t - strip * OH;      // row within strip
        const int n     = strip >> 1;
        const int ow0   = (strip & 1) ? (OW - 128) : 0;

        // ---- strip entry: stage planes oh..oh+2 (120 tasks, 12 warps) ----
        if (strip != prev_strip) {
            #pragma unroll 1
            for (int j = 0; j < 10; ++j) {
                int tk = wid + NWARPS * j;
                if (tk >= 120) break;
                int pl  = tk / 40;
                int r   = tk - pl * 40;
                int oct = r / 5;
                int cg  = r - oct * 5;
                stage_task(x, n, oh + pl, ow0, oct, cg, lane, sb);
            }
            BAR_ALL();
            prev_strip = strip;
        }
        // invariant: planes oh, oh+1, oh+2 staged & visible

        const bool next_same = (t + 1 < tEnd) && (oh + 1 < OH);

        if (consumer) {
            // ---- MMA: warp tile 32px x 64co; K = 9 kpos x 4 ksteps; f16 acc ----
            uint32_t acc[2][8][2];
            #pragma unroll
            for (int mi = 0; mi < 2; ++mi)
                #pragma unroll
                for (int nt = 0; nt < 8; ++nt) {
                    acc[mi][nt][0] = 0u;
                    acc[mi][nt][1] = 0u;
                }

            #pragma unroll 1
            for (int kp = 0; kp < KPOS; ++kp) {
                const int kh = kp / 3, kw = kp - 3 * (kp / 3);
                const uint32_t aKp = sb + OFF_S + (uint32_t)((oh + kh) & 3) * S_PLANEB
                                   + aCol + (uint32_t)kw * S_COLB;
                const uint32_t kB  = (uint32_t)(kp * 64) * 2;
                #pragma unroll
                for (int ks = 0; ks < 4; ++ks) {
                    uint32_t a0[4], a1[4];
                    LDSM_X4(a0, aKp + ks * 32);
                    LDSM_X4(a1, aKp + ks * 32 + 16 * S_COLB);
                    uint32_t bf[4][4];
                    #pragma unroll
                    for (int ntp = 0; ntp < 4; ++ntp)
                        LDSM_X4(bf[ntp], bBase + (uint32_t)ntp * 16 * W_ROWB + kB + ks * 32);
                    #pragma unroll
                    for (int ntp = 0; ntp < 4; ++ntp) {
                        mma_f16(acc[0][2 * ntp + 0], a0, &bf[ntp][0]);
                        mma_f16(acc[0][2 * ntp + 1], a0, &bf[ntp][2]);
                        mma_f16(acc[1][2 * ntp + 0], a1, &bf[ntp][0]);
                        mma_f16(acc[1][2 * ntp + 1], a1, &bf[ntp][2]);
                    }
                }
            }

            // ---- epilogue: half2 bias + min over this warp's 64 co ----
            float v4[4];  // [mi*2 + h]
            #pragma unroll
            for (int mi = 0; mi < 2; ++mi) {
                __half2 h0 = __floats2half2_rn(6.5e4f, 6.5e4f);
                __half2 h1 = h0;
                #pragma unroll
                for (int nt = 0; nt < 8; ++nt) {
                    h0 = __hmin2(h0, __hadd2(*(__half2*)&acc[mi][nt][0], bh[nt]));
                    h1 = __hmin2(h1, __hadd2(*(__half2*)&acc[mi][nt][1], bh[nt]));
                }
                float2 f0 = __half22float2(h0);
                float2 f1 = __half22float2(h1);
                v4[mi * 2 + 0] = fminf(f0.x, f0.y);
                v4[mi * 2 + 1] = fminf(f1.x, f1.y);
            }
            #pragma unroll
            for (int j = 0; j < 4; ++j) {
                v4[j] = fminf(v4[j], __shfl_xor_sync(0xFFFFFFFFu, v4[j], 1));
                v4[j] = fminf(v4[j], __shfl_xor_sync(0xFFFFFFFFu, v4[j], 2));
            }
            if ((lane & 3) == 0) {
                int row = lane >> 2;
                #pragma unroll
                for (int mi = 0; mi < 2; ++mi) {
                    int px0 = wm * 32 + mi * 16 + row;
                    min_sm[px0 * 2 + wn]       = v4[mi * 2 + 0];
                    min_sm[(px0 + 8) * 2 + wn] = v4[mi * 2 + 1];
                }
            }
            // pair barrier: only the two co-half warps of this pixel group
            BAR_PAIR(wm);
            if (wn == 0) {
                int px = wm * 32 + lane;   // this group's 32 pixels
                float2 q = *(const float2*)(min_sm + px * 2);
                float m = fminf(q.x, q.y);
                out[((size_t)n * OH + oh) * OW + ow0 + px] = tanhf(tanhf(m));
            }
        } else {
            // ---- producers (4 warps): stage plane oh+3 (10 tasks/warp) ----
            // slot (oh+3)&3 held plane oh-1; its last readers were in row oh-1.
            if (next_same) {
                const int pw = wid - 8;
                #pragma unroll
                for (int j = 0; j < 10; ++j) {
                    int tk  = pw + 4 * j;     // 0..39
                    int oct = tk / 5;
                    int cg  = tk - oct * 5;
                    stage_task(x, n, oh + 3, ow0, oct, cg, lane, sb);
                }
            }
        }

        BAR_ALL();  // plane oh+3 visible; min_sm reads done; ring slot retire
    }
}

extern "C" void kernel_launch(void* const* d_in, const int* in_sizes, int n_in,
                              void* d_out, int out_size)
{
    const float* x    = (const float*)d_in[0];
    const float* wgt  = (const float*)d_in[1];
    const float* bias = (const float*)d_in[2];
    float* out        = (float*)d_out;

    cudaFuncSetAttribute(conv_min_tanh_152,
                         cudaFuncAttributeMaxDynamicSharedMemorySize, SMEM_TOTAL);
    conv_min_tanh_152<<<NSM, THREADS, SMEM_TOTAL>>>(x, wgt, bias, out);
}